// round 2
// baseline (speedup 1.0000x reference)
#include <cuda_runtime.h>
#include <math.h>

// ---------------- static device scratch (no cudaMalloc allowed) -------------
#define MAXV    16384
#define MAXS    66
#define MAXPTS  (66*66*66)        // >= 65^3 with slack
#define LAUNCH_PTS (65*65*65)     // 274625, compile-time upper bound on grid pts
#define TPB     256
#define PPT     4                 // points per thread
#define VCHUNK  1024              // verts per block (smem tile)
#define WEPS    1e-6f

__device__ float  g_vn[MAXV*3];
__device__ float  g_dual[MAXV];
__device__ float4 g_vA[MAXV];     // x,y,z, na.x
__device__ float2 g_vB[MAXV];     // na.y, na.z
__device__ float  g_wsum[MAXPTS];
__device__ float  g_vol[MAXPTS];
__device__ float  g_axes[3][MAXS];
__device__ int    g_dims[4];      // sx, sy, sz, npts
__device__ int    g_b0[3];
__device__ int    g_bsz[3];
__device__ float  g_ratio[3];
__device__ int    g_faces64;      // 1 if faces buffer is int64, 0 if int32

__device__ __forceinline__ float fsqrt_ap(float x) {
    float r; asm("sqrt.approx.f32 %0, %1;" : "=f"(r) : "f"(x)); return r;
}
__device__ __forceinline__ float frcp_ap(float x) {
    float r; asm("rcp.approx.f32 %0, %1;" : "=f"(r) : "f"(x)); return r;
}

// ---------------- K0: zero accumulators -------------------------------------
__global__ void k_zero() {
    int i = blockIdx.x * blockDim.x + threadIdx.x;
    if (i < MAXV*3) g_vn[i]   = 0.0f;
    if (i < MAXV)   g_dual[i] = 0.0f;
    if (i < MAXPTS) g_wsum[i] = 0.0f;
}

// ---------------- K0b: detect faces dtype (int32 vs int64) ------------------
__global__ void k_detect(const int* __restrict__ f32, int n32) {
    if (threadIdx.x != 0 || blockIdx.x != 0) return;
    int lim = n32 < 4096 ? n32 : 4096;
    int any = 0;
    for (int i = 1; i < lim; i += 2) {
        if (f32[i] != 0) { any = 1; break; }
    }
    // int64 little-endian with small positive indices -> all odd dwords zero
    g_faces64 = any ? 0 : 1;
}

// ---------------- K1: bbox + grid layout ------------------------------------
__global__ void k_bbox(const float* __restrict__ verts, int V, int R) {
    __shared__ float s[6][256];
    int t = threadIdx.x;
    float mn0 = 1e30f, mn1 = 1e30f, mn2 = 1e30f;
    float mx0 = -1e30f, mx1 = -1e30f, mx2 = -1e30f;
    for (int v = t; v < V; v += 256) {
        float x = verts[3*v+0], y = verts[3*v+1], z = verts[3*v+2];
        mn0 = fminf(mn0, x); mx0 = fmaxf(mx0, x);
        mn1 = fminf(mn1, y); mx1 = fmaxf(mx1, y);
        mn2 = fminf(mn2, z); mx2 = fmaxf(mx2, z);
    }
    s[0][t] = mn0; s[1][t] = mn1; s[2][t] = mn2;
    s[3][t] = mx0; s[4][t] = mx1; s[5][t] = mx2;
    __syncthreads();
    for (int off = 128; off > 0; off >>= 1) {
        if (t < off) {
            s[0][t] = fminf(s[0][t], s[0][t+off]);
            s[1][t] = fminf(s[1][t], s[1][t+off]);
            s[2][t] = fminf(s[2][t], s[2][t+off]);
            s[3][t] = fmaxf(s[3][t], s[3][t+off]);
            s[4][t] = fmaxf(s[4][t], s[4][t+off]);
            s[5][t] = fmaxf(s[5][t], s[5][t+off]);
        }
        __syncthreads();
    }
    if (t == 0) {
        float bmin[3] = { s[0][0], s[1][0], s[2][0] };
        float bmax[3] = { s[3][0], s[4][0], s[5][0] };
        float blen[3], mb = 0.0f;
        for (int i = 0; i < 3; i++) { blen[i] = __fadd_rn(bmax[i], -bmin[i]); mb = fmaxf(mb, blen[i]); }
        float steplen = __fdiv_rn(mb, 64.0f);     // BBOX_DENSITY = 64
        int step[3];
        for (int i = 0; i < 3; i++) {
            int st = (int)__fdiv_rn(blen[i], steplen) + 1;   // trunc like astype(int64)
            if (st < 1) st = 1;
            if (st > 65) st = 65;
            step[i] = st;
        }
        g_dims[0] = step[0]; g_dims[1] = step[1]; g_dims[2] = step[2];
        g_dims[3] = step[0] * step[1] * step[2];
        float Rf = (float)R;
        for (int i = 0; i < 3; i++) {
            // numpy linspace: float64 math, endpoint forced; cast to f32
            int n = step[i];
            double a = (double)bmin[i], b = (double)bmax[i];
            if (n > 1) {
                double stp = (b - a) / (double)(n - 1);
                for (int j = 0; j < n; j++) g_axes[i][j] = (float)((double)j * stp + a);
                g_axes[i][n-1] = (float)b;
            } else {
                g_axes[i][0] = (float)a;
            }
            float lo = floorf(__fmul_rn(__fmul_rn(__fadd_rn(bmin[i], 1.0f), Rf), 0.5f));
            float hi = floorf(__fmul_rn(__fmul_rn(__fadd_rn(bmax[i], 1.0f), Rf), 0.5f));
            int b0 = (int)lo, b1 = (int)hi;
            g_b0[i] = b0;
            int bs = b1 - b0 + 1;
            if (bs < 1) bs = 1;
            g_bsz[i] = bs;
            g_ratio[i] = (float)((double)n / (double)bs);
        }
    }
}

// ---------------- K2: per-face cross + angle-weighted area scatter ----------
__global__ void k_faces(const float* __restrict__ verts,
                        const void* __restrict__ faces_raw, int F, int V) {
    int f = blockIdx.x * blockDim.x + threadIdx.x;
    if (f >= F) return;
    int i0, i1, i2;
    if (g_faces64) {
        const long long* ff = (const long long*)faces_raw;
        i0 = (int)ff[3*f+0]; i1 = (int)ff[3*f+1]; i2 = (int)ff[3*f+2];
    } else {
        const int* fi = (const int*)faces_raw;
        i0 = fi[3*f+0]; i1 = fi[3*f+1]; i2 = fi[3*f+2];
    }
    i0 = min(max(i0, 0), V-1); i1 = min(max(i1, 0), V-1); i2 = min(max(i2, 0), V-1);

    float v0x = verts[3*i0+0], v0y = verts[3*i0+1], v0z = verts[3*i0+2];
    float v1x = verts[3*i1+0], v1y = verts[3*i1+1], v1z = verts[3*i1+2];
    float v2x = verts[3*i2+0], v2y = verts[3*i2+1], v2z = verts[3*i2+2];

    float Ax = v1x - v0x, Ay = v1y - v0y, Az = v1z - v0z;
    float Bx = v2x - v1x, By = v2y - v1y, Bz = v2z - v1z;
    float Cx = v0x - v2x, Cy = v0y - v2y, Cz = v0z - v2z;
    float ex = v2x - v0x, ey = v2y - v0y, ez = v2z - v0z;

    float crx = Ay*ez - Az*ey;
    float cry = Az*ex - Ax*ez;
    float crz = Ax*ey - Ay*ex;
    float area = 0.5f * sqrtf(crx*crx + cry*cry + crz*crz);

    float nA = sqrtf(Ax*Ax + Ay*Ay + Az*Az);
    float nB = sqrtf(Bx*Bx + By*By + Bz*Bz);
    float nC = sqrtf(Cx*Cx + Cy*Cy + Cz*Cz);

    float d_ac = Ax*Cx + Ay*Cy + Az*Cz;
    float d_ab = Ax*Bx + Ay*By + Az*Bz;
    float d_bc = Bx*Cx + By*Cy + Bz*Cz;

    float a0 = acosf(fminf(fmaxf(-d_ac / (1e-10f + nA*nC), -1.0f), 1.0f));
    float a1 = acosf(fminf(fmaxf(-d_ab / (1e-10f + nA*nB), -1.0f), 1.0f));
    float a2 = acosf(fminf(fmaxf(-d_bc / (1e-10f + nB*nC), -1.0f), 1.0f));

    float s0 = sinf(2.0f*a0), s1 = sinf(2.0f*a1), s2 = sinf(2.0f*a2);
    float ssum = s0 + s1 + s2 + 1e-8f;
    float w0 = s0 / ssum, w1 = s1 / ssum, w2 = s2 / ssum;
    float wp0 = 0.5f * (w2 + w1);
    float wp1 = 0.5f * (w0 + w2);
    float wp2 = 0.5f * (w1 + w0);

    atomicAdd(&g_vn[3*i0+0], crx); atomicAdd(&g_vn[3*i0+1], cry); atomicAdd(&g_vn[3*i0+2], crz);
    atomicAdd(&g_vn[3*i1+0], crx); atomicAdd(&g_vn[3*i1+1], cry); atomicAdd(&g_vn[3*i1+2], crz);
    atomicAdd(&g_vn[3*i2+0], crx); atomicAdd(&g_vn[3*i2+1], cry); atomicAdd(&g_vn[3*i2+2], crz);
    atomicAdd(&g_dual[i0], wp0 * area);
    atomicAdd(&g_dual[i1], wp1 * area);
    atomicAdd(&g_dual[i2], wp2 * area);
}

// ---------------- K3: normalize normals, pack per-vertex data ---------------
__global__ void k_pack(const float* __restrict__ verts, int V, int Vpad) {
    int v = blockIdx.x * blockDim.x + threadIdx.x;
    if (v >= Vpad) return;
    if (v < V) {
        float nx = g_vn[3*v+0], ny = g_vn[3*v+1], nz = g_vn[3*v+2];
        float len = sqrtf(nx*nx + ny*ny + nz*nz);
        float il = 1.0f / fmaxf(len, 1e-12f);
        float d = g_dual[v];
        float sc = il * d;
        g_vA[v] = make_float4(verts[3*v+0], verts[3*v+1], verts[3*v+2], nx * sc);
        g_vB[v] = make_float2(ny * sc, nz * sc);
    } else {
        g_vA[v] = make_float4(0.f, 0.f, 0.f, 0.f);   // zero normal -> zero term
        g_vB[v] = make_float2(0.f, 0.f);
    }
}

// ---------------- K4: winding-number partial sums ---------------------------
__global__ void __launch_bounds__(TPB) k_wind() {
    __shared__ float4 sA[VCHUNK];
    __shared__ float2 sB[VCHUNK];
    const int npts = g_dims[3];
    const int pbase = blockIdx.x * (TPB * PPT);
    if (pbase >= npts) return;

    const int vbase = blockIdx.y * VCHUNK;
    for (int v = threadIdx.x; v < VCHUNK; v += TPB) {
        sA[v] = g_vA[vbase + v];
        sB[v] = g_vB[vbase + v];
    }
    __syncthreads();

    const int sx = g_dims[0], sy = g_dims[1];
    float px[PPT], py[PPT], pz[PPT], acc[PPT];
    int pidx[PPT]; bool val[PPT];
    #pragma unroll
    for (int p = 0; p < PPT; p++) {
        int pi = pbase + threadIdx.x + p * TPB;
        val[p] = (pi < npts);
        int q = val[p] ? pi : 0;
        int ix = q % sx;
        int r  = q / sx;
        int jy = r % sy;
        int kz = r / sy;
        px[p] = g_axes[0][ix];
        py[p] = g_axes[1][jy];
        pz[p] = g_axes[2][kz];
        acc[p] = 0.0f;
        pidx[p] = pi;
    }

    #pragma unroll 2
    for (int v = 0; v < VCHUNK; v++) {
        float4 a = sA[v];
        float2 b = sB[v];
        #pragma unroll
        for (int p = 0; p < PPT; p++) {
            float dx = a.x - px[p];
            float dy = a.y - py[p];
            float dz = a.z - pz[p];
            float r2 = fmaf(dx, dx, fmaf(dy, dy, dz*dz));
            float dt = fmaf(dx, a.w, fmaf(dy, b.x, dz*b.y));
            float r  = fsqrt_ap(r2);           // sqrt.approx(0) = 0 (safe)
            float r3 = r2 * r;
            float inv = frcp_ap(r3 + WEPS);
            acc[p] = fmaf(dt, inv, acc[p]);
        }
    }

    #pragma unroll
    for (int p = 0; p < PPT; p++)
        if (val[p]) atomicAdd(&g_wsum[pidx[p]], acc[p]);
}

// ---------------- K4b: sigmoid --------------------------------------------
__global__ void k_sig() {
    int i = blockIdx.x * blockDim.x + threadIdx.x;
    if (i >= g_dims[3]) return;
    float w = g_wsum[i] / 12.566370614359172f;     // / (4*pi)
    float x = (w - 0.5f) * 100.0f;
    g_vol[i] = 1.0f / (1.0f + __expf(-x));
}

// ---------------- K5: trilerp + scatter into R^3, transposed ---------------
__global__ void k_out(float* __restrict__ out, int R, int total) {
    int n = blockIdx.x * blockDim.x + threadIdx.x;
    if (n >= total) return;
    // out[n] with n = (i*R + j)*R + k maps to whole[k, j, i] (transpose(2,1,0))
    int k = n % R;
    int t = n / R;
    int j = t % R;
    int i = t / R;
    int a = k, b = j, c = i;              // whole axes (x, y, z)
    float val = 0.0f;
    int bi = a - g_b0[0], bj = b - g_b0[1], bk = c - g_b0[2];
    int bsx = g_bsz[0], bsy = g_bsz[1], bsz_ = g_bsz[2];
    if (bi >= 0 && bi < bsx && bj >= 0 && bj < bsy && bk >= 0 && bk < bsz_) {
        int sx = g_dims[0], sy = g_dims[1], sz = g_dims[2];
        float c0 = ((float)bi + 0.5f) * g_ratio[0] - 0.5f;
        float c1 = ((float)bj + 0.5f) * g_ratio[1] - 0.5f;
        float c2 = ((float)bk + 0.5f) * g_ratio[2] - 0.5f;
        c0 = fminf(fmaxf(c0, 0.0f), (float)(sx - 1));
        c1 = fminf(fmaxf(c1, 0.0f), (float)(sy - 1));
        c2 = fminf(fmaxf(c2, 0.0f), (float)(sz - 1));
        int i0 = (int)c0, j0 = (int)c1, k0 = (int)c2;
        float t0 = c0 - (float)i0, t1 = c1 - (float)j0, t2 = c2 - (float)k0;
        int i1 = min(i0 + 1, sx - 1);
        int j1 = min(j0 + 1, sy - 1);
        int k1 = min(k0 + 1, sz - 1);
        // vol stored x-fastest: idx = (kz*sy + jy)*sx + ix
        #define VOL(I,J,K) g_vol[((K)*sy + (J))*sx + (I)]
        float v000 = VOL(i0, j0, k0), v100 = VOL(i1, j0, k0);
        float v010 = VOL(i0, j1, k0), v110 = VOL(i1, j1, k0);
        float v001 = VOL(i0, j0, k1), v101 = VOL(i1, j0, k1);
        float v011 = VOL(i0, j1, k1), v111 = VOL(i1, j1, k1);
        #undef VOL
        float x00 = v000 + t0 * (v100 - v000);
        float x10 = v010 + t0 * (v110 - v010);
        float x01 = v001 + t0 * (v101 - v001);
        float x11 = v011 + t0 * (v111 - v011);
        float y0 = x00 + t1 * (x10 - x00);
        float y1 = x01 + t1 * (x11 - x01);
        val = y0 + t2 * (y1 - y0);
    }
    out[n] = val;
}

// ---------------- launcher ---------------------------------------------------
extern "C" void kernel_launch(void* const* d_in, const int* in_sizes, int n_in,
                              void* d_out, int out_size) {
    const float* verts = (const float*)d_in[0];
    const void*  faces = (const void*)d_in[1];
    int V = in_sizes[0] / 3;
    int F = in_sizes[1] / 3;
    if (V > MAXV) V = MAXV;
    int Vpad = ((V + VCHUNK - 1) / VCHUNK) * VCHUNK;
    if (Vpad > MAXV) Vpad = MAXV;

    double cr = cbrt((double)out_size);
    int R = (int)(cr + 0.5);

    k_zero<<<(MAXPTS + 255) / 256, 256>>>();
    k_detect<<<1, 32>>>((const int*)faces, in_sizes[1] * 2); // safe upper scan bound in dwords if int64; detector clamps
    k_bbox<<<1, 256>>>(verts, V, R);
    k_faces<<<(F + 255) / 256, 256>>>(verts, faces, F, V);
    k_pack<<<(Vpad + 255) / 256, 256>>>(verts, V, Vpad);

    dim3 gw((LAUNCH_PTS + TPB * PPT - 1) / (TPB * PPT), Vpad / VCHUNK);
    k_wind<<<gw, TPB>>>();

    k_sig<<<(LAUNCH_PTS + 255) / 256, 256>>>();
    k_out<<<(out_size + 255) / 256, 256>>>((float*)d_out, R, out_size);
}

// round 3
// speedup vs baseline: 1.2124x; 1.2124x over previous
#include <cuda_runtime.h>
#include <math.h>

// ---------------- static device scratch (no cudaMalloc allowed) -------------
#define MAXV    16384
#define MAXS    66
#define MAXPTS  (66*66*66)
#define LAUNCH_PTS (65*65*65)     // 274625 compile-time upper bound on grid pts
#define TPB     256
#define PPT     4                 // points per thread (2 packed f32x2 pairs)
#define VCHUNK  256               // verts per block (smem tile) == TPB
#define WEPS    1e-6f

typedef unsigned long long u64;

__device__ float  g_vn[MAXV*3];
__device__ float  g_dual[MAXV];
__device__ float4 g_vA[MAXV];     // x,y,z, na.x
__device__ float2 g_vB[MAXV];     // na.y, na.z
__device__ float  g_wsum[MAXPTS];
__device__ float  g_vol[MAXPTS];
__device__ float  g_axes[3][MAXS];
__device__ int    g_dims[4];      // sx, sy, sz, npts
__device__ int    g_b0[3];
__device__ int    g_bsz[3];
__device__ float  g_ratio[3];
__device__ int    g_faces64;      // 1 if faces buffer is int64, 0 if int32

__device__ __forceinline__ float fsqrt_ap(float x) {
    float r; asm("sqrt.approx.f32 %0, %1;" : "=f"(r) : "f"(x)); return r;
}
__device__ __forceinline__ float frcp_ap(float x) {
    float r; asm("rcp.approx.f32 %0, %1;" : "=f"(r) : "f"(x)); return r;
}
// ---- packed f32x2 helpers (sm_100+) ----
__device__ __forceinline__ u64 f2_add(u64 a, u64 b) {
    u64 r; asm("add.rn.f32x2 %0, %1, %2;" : "=l"(r) : "l"(a), "l"(b)); return r;
}
__device__ __forceinline__ u64 f2_mul(u64 a, u64 b) {
    u64 r; asm("mul.rn.f32x2 %0, %1, %2;" : "=l"(r) : "l"(a), "l"(b)); return r;
}
__device__ __forceinline__ u64 f2_fma(u64 a, u64 b, u64 c) {
    u64 r; asm("fma.rn.f32x2 %0, %1, %2, %3;" : "=l"(r) : "l"(a), "l"(b), "l"(c)); return r;
}
__device__ __forceinline__ u64 f2_pack(float lo, float hi) {
    u64 r; asm("mov.b64 %0, {%1, %2};" : "=l"(r) : "f"(lo), "f"(hi)); return r;
}
__device__ __forceinline__ void f2_unpack(u64 v, float& lo, float& hi) {
    asm("mov.b64 {%0, %1}, %2;" : "=f"(lo), "=f"(hi) : "l"(v));
}

// ---------------- K0: zero accumulators -------------------------------------
__global__ void k_zero() {
    int i = blockIdx.x * blockDim.x + threadIdx.x;
    if (i < MAXV*3) g_vn[i]   = 0.0f;
    if (i < MAXV)   g_dual[i] = 0.0f;
    if (i < MAXPTS) g_wsum[i] = 0.0f;
}

// ---------------- K0b: detect faces dtype (int32 vs int64) ------------------
__global__ void k_detect(const int* __restrict__ f32, int n32) {
    if (threadIdx.x != 0 || blockIdx.x != 0) return;
    int lim = n32 < 4096 ? n32 : 4096;
    int any = 0;
    for (int i = 1; i < lim; i += 2) {
        if (f32[i] != 0) { any = 1; break; }
    }
    g_faces64 = any ? 0 : 1;   // int64 LE small indices -> all odd dwords zero
}

// ---------------- K1: bbox + grid layout ------------------------------------
__global__ void k_bbox(const float* __restrict__ verts, int V, int R) {
    __shared__ float s[6][256];
    int t = threadIdx.x;
    float mn0 = 1e30f, mn1 = 1e30f, mn2 = 1e30f;
    float mx0 = -1e30f, mx1 = -1e30f, mx2 = -1e30f;
    for (int v = t; v < V; v += 256) {
        float x = verts[3*v+0], y = verts[3*v+1], z = verts[3*v+2];
        mn0 = fminf(mn0, x); mx0 = fmaxf(mx0, x);
        mn1 = fminf(mn1, y); mx1 = fmaxf(mx1, y);
        mn2 = fminf(mn2, z); mx2 = fmaxf(mx2, z);
    }
    s[0][t] = mn0; s[1][t] = mn1; s[2][t] = mn2;
    s[3][t] = mx0; s[4][t] = mx1; s[5][t] = mx2;
    __syncthreads();
    for (int off = 128; off > 0; off >>= 1) {
        if (t < off) {
            s[0][t] = fminf(s[0][t], s[0][t+off]);
            s[1][t] = fminf(s[1][t], s[1][t+off]);
            s[2][t] = fminf(s[2][t], s[2][t+off]);
            s[3][t] = fmaxf(s[3][t], s[3][t+off]);
            s[4][t] = fmaxf(s[4][t], s[4][t+off]);
            s[5][t] = fmaxf(s[5][t], s[5][t+off]);
        }
        __syncthreads();
    }
    if (t == 0) {
        float bmin[3] = { s[0][0], s[1][0], s[2][0] };
        float bmax[3] = { s[3][0], s[4][0], s[5][0] };
        float blen[3], mb = 0.0f;
        for (int i = 0; i < 3; i++) { blen[i] = __fadd_rn(bmax[i], -bmin[i]); mb = fmaxf(mb, blen[i]); }
        float steplen = __fdiv_rn(mb, 64.0f);     // BBOX_DENSITY = 64
        int step[3];
        for (int i = 0; i < 3; i++) {
            int st = (int)__fdiv_rn(blen[i], steplen) + 1;
            if (st < 1) st = 1;
            if (st > 65) st = 65;
            step[i] = st;
        }
        g_dims[0] = step[0]; g_dims[1] = step[1]; g_dims[2] = step[2];
        g_dims[3] = step[0] * step[1] * step[2];
        float Rf = (float)R;
        for (int i = 0; i < 3; i++) {
            int n = step[i];
            double a = (double)bmin[i], b = (double)bmax[i];
            if (n > 1) {
                double stp = (b - a) / (double)(n - 1);
                for (int j = 0; j < n; j++) g_axes[i][j] = (float)((double)j * stp + a);
                g_axes[i][n-1] = (float)b;
            } else {
                g_axes[i][0] = (float)a;
            }
            float lo = floorf(__fmul_rn(__fmul_rn(__fadd_rn(bmin[i], 1.0f), Rf), 0.5f));
            float hi = floorf(__fmul_rn(__fmul_rn(__fadd_rn(bmax[i], 1.0f), Rf), 0.5f));
            int b0 = (int)lo, b1 = (int)hi;
            g_b0[i] = b0;
            int bs = b1 - b0 + 1;
            if (bs < 1) bs = 1;
            g_bsz[i] = bs;
            g_ratio[i] = (float)((double)n / (double)bs);
        }
    }
}

// ---------------- K2: per-face cross + angle-weighted area scatter ----------
__global__ void k_faces(const float* __restrict__ verts,
                        const void* __restrict__ faces_raw, int F, int V) {
    int f = blockIdx.x * blockDim.x + threadIdx.x;
    if (f >= F) return;
    int i0, i1, i2;
    if (g_faces64) {
        const long long* ff = (const long long*)faces_raw;
        i0 = (int)ff[3*f+0]; i1 = (int)ff[3*f+1]; i2 = (int)ff[3*f+2];
    } else {
        const int* fi = (const int*)faces_raw;
        i0 = fi[3*f+0]; i1 = fi[3*f+1]; i2 = fi[3*f+2];
    }
    i0 = min(max(i0, 0), V-1); i1 = min(max(i1, 0), V-1); i2 = min(max(i2, 0), V-1);

    float v0x = verts[3*i0+0], v0y = verts[3*i0+1], v0z = verts[3*i0+2];
    float v1x = verts[3*i1+0], v1y = verts[3*i1+1], v1z = verts[3*i1+2];
    float v2x = verts[3*i2+0], v2y = verts[3*i2+1], v2z = verts[3*i2+2];

    float Ax = v1x - v0x, Ay = v1y - v0y, Az = v1z - v0z;
    float Bx = v2x - v1x, By = v2y - v1y, Bz = v2z - v1z;
    float Cx = v0x - v2x, Cy = v0y - v2y, Cz = v0z - v2z;
    float ex = v2x - v0x, ey = v2y - v0y, ez = v2z - v0z;

    float crx = Ay*ez - Az*ey;
    float cry = Az*ex - Ax*ez;
    float crz = Ax*ey - Ay*ex;
    float area = 0.5f * sqrtf(crx*crx + cry*cry + crz*crz);

    float nA = sqrtf(Ax*Ax + Ay*Ay + Az*Az);
    float nB = sqrtf(Bx*Bx + By*By + Bz*Bz);
    float nC = sqrtf(Cx*Cx + Cy*Cy + Cz*Cz);

    float d_ac = Ax*Cx + Ay*Cy + Az*Cz;
    float d_ab = Ax*Bx + Ay*By + Az*Bz;
    float d_bc = Bx*Cx + By*Cy + Bz*Cz;

    float a0 = acosf(fminf(fmaxf(-d_ac / (1e-10f + nA*nC), -1.0f), 1.0f));
    float a1 = acosf(fminf(fmaxf(-d_ab / (1e-10f + nA*nB), -1.0f), 1.0f));
    float a2 = acosf(fminf(fmaxf(-d_bc / (1e-10f + nB*nC), -1.0f), 1.0f));

    float s0 = sinf(2.0f*a0), s1 = sinf(2.0f*a1), s2 = sinf(2.0f*a2);
    float ssum = s0 + s1 + s2 + 1e-8f;
    float w0 = s0 / ssum, w1 = s1 / ssum, w2 = s2 / ssum;
    float wp0 = 0.5f * (w2 + w1);
    float wp1 = 0.5f * (w0 + w2);
    float wp2 = 0.5f * (w1 + w0);

    atomicAdd(&g_vn[3*i0+0], crx); atomicAdd(&g_vn[3*i0+1], cry); atomicAdd(&g_vn[3*i0+2], crz);
    atomicAdd(&g_vn[3*i1+0], crx); atomicAdd(&g_vn[3*i1+1], cry); atomicAdd(&g_vn[3*i1+2], crz);
    atomicAdd(&g_vn[3*i2+0], crx); atomicAdd(&g_vn[3*i2+1], cry); atomicAdd(&g_vn[3*i2+2], crz);
    atomicAdd(&g_dual[i0], wp0 * area);
    atomicAdd(&g_dual[i1], wp1 * area);
    atomicAdd(&g_dual[i2], wp2 * area);
}

// ---------------- K3: normalize normals, pack per-vertex data ---------------
__global__ void k_pack(const float* __restrict__ verts, int V, int Vpad) {
    int v = blockIdx.x * blockDim.x + threadIdx.x;
    if (v >= Vpad) return;
    if (v < V) {
        float nx = g_vn[3*v+0], ny = g_vn[3*v+1], nz = g_vn[3*v+2];
        float len = sqrtf(nx*nx + ny*ny + nz*nz);
        float il = 1.0f / fmaxf(len, 1e-12f);
        float d = g_dual[v];
        float sc = il * d;
        g_vA[v] = make_float4(verts[3*v+0], verts[3*v+1], verts[3*v+2], nx * sc);
        g_vB[v] = make_float2(ny * sc, nz * sc);
    } else {
        g_vA[v] = make_float4(0.f, 0.f, 0.f, 0.f);   // zero normal -> zero term
        g_vB[v] = make_float2(0.f, 0.f);
    }
}

// ---------------- K4: winding-number partial sums (packed f32x2) ------------
__global__ void __launch_bounds__(TPB, 4) k_wind() {
    // duplicated-pair layout: one LDS.128 yields two f32x2 broadcast operands
    __shared__ float4 sA[VCHUNK];   // (x,x,y,y)
    __shared__ float4 sB[VCHUNK];   // (z,z,nx,nx)
    __shared__ float4 sC[VCHUNK];   // (ny,ny,nz,nz)
    const int npts = g_dims[3];
    const int pbase = blockIdx.x * (TPB * PPT);
    if (pbase >= npts) return;

    {
        int v  = threadIdx.x;              // VCHUNK == TPB
        int gv = blockIdx.y * VCHUNK + v;
        float4 A = g_vA[gv];
        float2 B = g_vB[gv];
        sA[v] = make_float4(A.x, A.x, A.y, A.y);
        sB[v] = make_float4(A.z, A.z, A.w, A.w);
        sC[v] = make_float4(B.x, B.x, B.y, B.y);
    }
    __syncthreads();

    const int sx = g_dims[0], sy = g_dims[1];
    float npx[PPT], npy[PPT], npz[PPT];
    int pidx[PPT]; bool val[PPT];
    #pragma unroll
    for (int p = 0; p < PPT; p++) {
        int pi = pbase + threadIdx.x + p * TPB;
        val[p] = (pi < npts);
        int q = val[p] ? pi : 0;
        int ix = q % sx;
        int r  = q / sx;
        int jy = r % sy;
        int kz = r / sy;
        npx[p] = -g_axes[0][ix];      // negated: dx = vx + (-px)
        npy[p] = -g_axes[1][jy];
        npz[p] = -g_axes[2][kz];
        pidx[p] = pi;
    }
    u64 px2[2], py2[2], pz2[2], acc[2];
    #pragma unroll
    for (int i = 0; i < 2; i++) {
        px2[i] = f2_pack(npx[2*i], npx[2*i+1]);
        py2[i] = f2_pack(npy[2*i], npy[2*i+1]);
        pz2[i] = f2_pack(npz[2*i], npz[2*i+1]);
        acc[i] = f2_pack(0.0f, 0.0f);
    }
    const u64 EPS2 = f2_pack(WEPS, WEPS);

    #pragma unroll 4
    for (int v = 0; v < VCHUNK; v++) {
        float4 A = sA[v], B = sB[v], C = sC[v];
        u64 vx  = f2_pack(A.x, A.y);
        u64 vy  = f2_pack(A.z, A.w);
        u64 vz  = f2_pack(B.x, B.y);
        u64 vnx = f2_pack(B.z, B.w);
        u64 vny = f2_pack(C.x, C.y);
        u64 vnz = f2_pack(C.z, C.w);
        #pragma unroll
        for (int i = 0; i < 2; i++) {
            u64 dx = f2_add(vx, px2[i]);
            u64 dy = f2_add(vy, py2[i]);
            u64 dz = f2_add(vz, pz2[i]);
            u64 r2 = f2_mul(dz, dz);
            r2 = f2_fma(dy, dy, r2);
            r2 = f2_fma(dx, dx, r2);
            u64 dt = f2_mul(dz, vnz);
            dt = f2_fma(dy, vny, dt);
            dt = f2_fma(dx, vnx, dt);
            float r2l, r2h; f2_unpack(r2, r2l, r2h);
            u64 rr = f2_pack(fsqrt_ap(r2l), fsqrt_ap(r2h));
            u64 r3 = f2_mul(r2, rr);
            u64 dd = f2_add(r3, EPS2);
            float dl, dh; f2_unpack(dd, dl, dh);
            u64 inv = f2_pack(frcp_ap(dl), frcp_ap(dh));
            acc[i] = f2_fma(dt, inv, acc[i]);
        }
    }

    float av[PPT];
    f2_unpack(acc[0], av[0], av[1]);
    f2_unpack(acc[1], av[2], av[3]);
    #pragma unroll
    for (int p = 0; p < PPT; p++)
        if (val[p]) atomicAdd(&g_wsum[pidx[p]], av[p]);
}

// ---------------- K4b: sigmoid ---------------------------------------------
__global__ void k_sig() {
    int i = blockIdx.x * blockDim.x + threadIdx.x;
    if (i >= g_dims[3]) return;
    float w = g_wsum[i] / 12.566370614359172f;     // / (4*pi)
    float x = (w - 0.5f) * 100.0f;
    g_vol[i] = 1.0f / (1.0f + __expf(-x));
}

// ---------------- K5: trilerp + scatter into R^3, transposed ----------------
__global__ void k_out(float* __restrict__ out, int R, int total) {
    int n = blockIdx.x * blockDim.x + threadIdx.x;
    if (n >= total) return;
    int k = n % R;
    int t = n / R;
    int j = t % R;
    int i = t / R;
    int a = k, b = j, c = i;              // whole axes (x, y, z)
    float val = 0.0f;
    int bi = a - g_b0[0], bj = b - g_b0[1], bk = c - g_b0[2];
    int bsx = g_bsz[0], bsy = g_bsz[1], bsz_ = g_bsz[2];
    if (bi >= 0 && bi < bsx && bj >= 0 && bj < bsy && bk >= 0 && bk < bsz_) {
        int sx = g_dims[0], sy = g_dims[1], sz = g_dims[2];
        float c0 = ((float)bi + 0.5f) * g_ratio[0] - 0.5f;
        float c1 = ((float)bj + 0.5f) * g_ratio[1] - 0.5f;
        float c2 = ((float)bk + 0.5f) * g_ratio[2] - 0.5f;
        c0 = fminf(fmaxf(c0, 0.0f), (float)(sx - 1));
        c1 = fminf(fmaxf(c1, 0.0f), (float)(sy - 1));
        c2 = fminf(fmaxf(c2, 0.0f), (float)(sz - 1));
        int i0 = (int)c0, j0 = (int)c1, k0 = (int)c2;
        float t0 = c0 - (float)i0, t1 = c1 - (float)j0, t2 = c2 - (float)k0;
        int i1 = min(i0 + 1, sx - 1);
        int j1 = min(j0 + 1, sy - 1);
        int k1 = min(k0 + 1, sz - 1);
        #define VOL(I,J,K) g_vol[((K)*sy + (J))*sx + (I)]
        float v000 = VOL(i0, j0, k0), v100 = VOL(i1, j0, k0);
        float v010 = VOL(i0, j1, k0), v110 = VOL(i1, j1, k0);
        float v001 = VOL(i0, j0, k1), v101 = VOL(i1, j0, k1);
        float v011 = VOL(i0, j1, k1), v111 = VOL(i1, j1, k1);
        #undef VOL
        float x00 = v000 + t0 * (v100 - v000);
        float x10 = v010 + t0 * (v110 - v010);
        float x01 = v001 + t0 * (v101 - v001);
        float x11 = v011 + t0 * (v111 - v011);
        float y0 = x00 + t1 * (x10 - x00);
        float y1 = x01 + t1 * (x11 - x01);
        val = y0 + t2 * (y1 - y0);
    }
    out[n] = val;
}

// ---------------- launcher ---------------------------------------------------
extern "C" void kernel_launch(void* const* d_in, const int* in_sizes, int n_in,
                              void* d_out, int out_size) {
    const float* verts = (const float*)d_in[0];
    const void*  faces = (const void*)d_in[1];
    int V = in_sizes[0] / 3;
    int F = in_sizes[1] / 3;
    if (V > MAXV) V = MAXV;
    int Vpad = ((V + VCHUNK - 1) / VCHUNK) * VCHUNK;
    if (Vpad > MAXV) Vpad = MAXV;

    double cr = cbrt((double)out_size);
    int R = (int)(cr + 0.5);

    k_zero<<<(MAXPTS + 255) / 256, 256>>>();
    k_detect<<<1, 32>>>((const int*)faces, in_sizes[1] * 2);
    k_bbox<<<1, 256>>>(verts, V, R);
    k_faces<<<(F + 255) / 256, 256>>>(verts, faces, F, V);
    k_pack<<<(Vpad + 255) / 256, 256>>>(verts, V, Vpad);

    dim3 gw((LAUNCH_PTS + TPB * PPT - 1) / (TPB * PPT), Vpad / VCHUNK);
    k_wind<<<gw, TPB>>>();

    k_sig<<<(LAUNCH_PTS + 255) / 256, 256>>>();
    k_out<<<(out_size + 255) / 256, 256>>>((float*)d_out, R, out_size);
}